// round 2
// baseline (speedup 1.0000x reference)
#include <cuda_runtime.h>
#include <cuda_bf16.h>
#include <cstdint>

// Problem constants
#define N_NODE 40000
#define N_EDGE 320000
#define DIM    1024

// ---------------- device scratch (no cudaMalloc allowed) ----------------
__device__ int   g_deg[N_NODE];
__device__ int   g_offs[N_NODE + 1];
__device__ int   g_cursor[N_NODE];
__device__ int   g_sorted_src[N_EDGE];
__device__ float g_agg0[(size_t)N_NODE * DIM];   // 160 MB
__device__ float g_agg1[(size_t)N_NODE * DIM];   // 160 MB (second chunk for fused prot GEMM)

// ---------------- small helpers ----------------
__device__ __forceinline__ uint32_t f2tf32(float x) {
    uint32_t r;
    asm("cvt.rna.tf32.f32 %0, %1;" : "=r"(r) : "f"(x));
    return r;
}

__device__ __forceinline__ void mma_tf32(float& c0, float& c1, float& c2, float& c3,
                                         uint32_t a0, uint32_t a1, uint32_t a2, uint32_t a3,
                                         uint32_t b0, uint32_t b1) {
    asm volatile(
        "mma.sync.aligned.m16n8k8.row.col.f32.tf32.tf32.f32 "
        "{%0,%1,%2,%3}, {%4,%5,%6,%7}, {%8,%9}, {%0,%1,%2,%3};"
        : "+f"(c0), "+f"(c1), "+f"(c2), "+f"(c3)
        : "r"(a0), "r"(a1), "r"(a2), "r"(a3), "r"(b0), "r"(b1));
}

// ---------------- sort-by-dst pipeline ----------------
__global__ void zero_deg_kernel() {
    int i = blockIdx.x * blockDim.x + threadIdx.x;
    if (i < N_NODE) g_deg[i] = 0;
}

__global__ void hist_kernel(const int* __restrict__ dst) {
    int i = blockIdx.x * blockDim.x + threadIdx.x;
    if (i < N_EDGE) atomicAdd(&g_deg[dst[i]], 1);
}

// single-block exclusive scan of g_deg -> g_offs (and g_cursor copy)
__global__ void scan_kernel() {
    __shared__ int sh[1024];
    __shared__ int carry;
    int t = threadIdx.x;
    if (t == 0) carry = 0;
    __syncthreads();
    for (int base = 0; base < N_NODE; base += 1024) {
        int idx = base + t;
        int v = (idx < N_NODE) ? g_deg[idx] : 0;
        sh[t] = v;
        __syncthreads();
        #pragma unroll
        for (int off = 1; off < 1024; off <<= 1) {
            int x = (t >= off) ? sh[t - off] : 0;
            __syncthreads();
            sh[t] += x;
            __syncthreads();
        }
        int incl = sh[t];
        int excl = incl - v;
        int c = carry;
        if (idx < N_NODE) {
            g_offs[idx]   = c + excl;
            g_cursor[idx] = c + excl;
        }
        int total = sh[1023];
        __syncthreads();
        if (t == 0) carry = c + total;
        __syncthreads();
    }
    if (t == 0) g_offs[N_NODE] = carry;
}

__global__ void scatter_kernel(const int* __restrict__ src, const int* __restrict__ dst) {
    int i = blockIdx.x * blockDim.x + threadIdx.x;
    if (i < N_EDGE) {
        int pos = atomicAdd(&g_cursor[dst[i]], 1);
        g_sorted_src[pos] = src[i];
    }
}

// one block (256 threads) per destination node; each thread owns one float4 of the row
__global__ void aggregate_kernel(const float* __restrict__ xsrc, float* __restrict__ aggout) {
    int v = blockIdx.x;
    int beg = g_offs[v];
    int end = g_offs[v + 1];
    int t = threadIdx.x;

    float4 acc = make_float4(0.f, 0.f, 0.f, 0.f);
    const float4* xs = reinterpret_cast<const float4*>(xsrc);
    int e = beg;
    for (; e + 1 < end; e += 2) {
        int s0 = g_sorted_src[e];
        int s1 = g_sorted_src[e + 1];
        float4 r0 = xs[(size_t)s0 * (DIM / 4) + t];
        float4 r1 = xs[(size_t)s1 * (DIM / 4) + t];
        acc.x += r0.x + r1.x; acc.y += r0.y + r1.y;
        acc.z += r0.z + r1.z; acc.w += r0.w + r1.w;
    }
    if (e < end) {
        int s = g_sorted_src[e];
        float4 r = xs[(size_t)s * (DIM / 4) + t];
        acc.x += r.x; acc.y += r.y; acc.z += r.z; acc.w += r.w;
    }
    int d = end - beg;
    float inv = 1.0f / (float)(d > 1 ? d : 1);
    acc.x *= inv; acc.y *= inv; acc.z *= inv; acc.w *= inv;
    reinterpret_cast<float4*>(aggout)[(size_t)v * (DIM / 4) + t] = acc;
}

// ---------------- pipelined TF32 GEMM ----------------
// C[M,1024] = sum_chunk A_c[M,1024] @ W_c[1024,1024]  + bias0 (+ bias1)
// BM=128 BN=128 BK=16, 256 threads (8 warps: 2x4), warp tile 64x32.
// Double-buffered smem + register prefetch; fragment-permuted smem layout
// so the mainloop issues only conflict-free LDS.128/LDS.64.
template <int CHUNKS>
__global__ __launch_bounds__(256, 1) void gemm_tf32_pipe(
    const float* __restrict__ A0, const float* __restrict__ A1,
    const float* __restrict__ W0, const float* __restrict__ W1,
    const float* __restrict__ bias0, const float* __restrict__ bias1,
    float* __restrict__ C, int M)
{
    __shared__ uint32_t Asm[2][2048];  // 128x16 permuted, double buffered
    __shared__ uint32_t Bsm[2][2048];  // 16x128 permuted, double buffered

    const int t      = threadIdx.x;
    const int lane   = t & 31;
    const int warp   = t >> 5;
    const int warp_m = warp >> 2;   // 0..1
    const int warp_n = warp & 3;    // 0..3
    const int g      = lane >> 2;   // groupID
    const int tid4   = lane & 3;    // threadID_in_group
    const int bm     = blockIdx.y * 128;
    const int bn     = blockIdx.x * 128;

    // ---- precompute loop-invariant staging indices ----
    // A: idx = t + i*256 -> m = idx>>2 (row in tile), kq = idx&3 (float4 along k)
    int a_m[2], a_kq, a_soff[2][4];
    a_kq = t & 3;
    #pragma unroll
    for (int i = 0; i < 2; i++) {
        int idx = t + i * 256;
        int m = idx >> 2;
        a_m[i] = m;
        #pragma unroll
        for (int j = 0; j < 4; j++) {
            int k     = a_kq * 4 + j;
            int wm    = m >> 6;
            int mtile = (m & 63) >> 4;
            int r16   = m & 15;
            int gg    = r16 & 7;
            int rowh  = r16 >> 3;
            int kstep = k >> 3;
            int kk    = k & 7;
            int ti    = kk & 3;
            int colh  = kk >> 2;
            int reg   = colh * 2 + rowh;
            int ln    = gg * 4 + ti;
            a_soff[i][j] = (((wm * 4 + mtile) * 2 + kstep) * 128) + ln * 4 + reg;
        }
    }
    // B: idx = t + i*256 -> kr = idx>>5, nq = idx&31
    int b_kr[2], b_nq, b_soff[2][4];
    b_nq = t & 31;
    #pragma unroll
    for (int i = 0; i < 2; i++) {
        int idx = t + i * 256;
        b_kr[i] = idx >> 5;
        #pragma unroll
        for (int j = 0; j < 4; j++) {
            int n     = b_nq * 4 + j;
            int wn    = n >> 5;
            int ntile = (n & 31) >> 3;
            int gg    = n & 7;
            int kr    = b_kr[i];
            int kstep = kr >> 3;
            int kk    = kr & 7;
            int ti    = kk & 3;
            int reg   = kk >> 2;
            int ln    = gg * 4 + ti;
            b_soff[i][j] = (((wn * 4 + ntile) * 2 + kstep) * 64) + ln * 2 + reg;
        }
    }

    float c[4][4][4];
    #pragma unroll
    for (int mt = 0; mt < 4; mt++)
        #pragma unroll
        for (int nt = 0; nt < 4; nt++)
            #pragma unroll
            for (int r = 0; r < 4; r++) c[mt][nt][r] = 0.f;

    const int KT = 64 * CHUNKS;
    float4 va[2], vb[2];

    // ---- gmem load of tile kt into registers ----
    auto load_tile = [&](int kt) {
        const float* Asrc = (CHUNKS == 2 && kt >= 64) ? A1 : A0;
        const float* Wsrc = (CHUNKS == 2 && kt >= 64) ? W1 : W0;
        const int k0 = (kt & 63) * 16;
        #pragma unroll
        for (int i = 0; i < 2; i++) {
            int gm = bm + a_m[i];
            va[i] = (gm < M)
                ? reinterpret_cast<const float4*>(Asrc + (size_t)gm * DIM + k0)[a_kq]
                : make_float4(0.f, 0.f, 0.f, 0.f);
        }
        #pragma unroll
        for (int i = 0; i < 2; i++) {
            vb[i] = reinterpret_cast<const float4*>(
                Wsrc + (size_t)(k0 + b_kr[i]) * DIM + bn + b_nq * 4)[0];
        }
    };

    // ---- store registers into permuted smem buffer ----
    auto store_tile = [&](int buf) {
        #pragma unroll
        for (int i = 0; i < 2; i++) {
            float vv[4] = {va[i].x, va[i].y, va[i].z, va[i].w};
            #pragma unroll
            for (int j = 0; j < 4; j++) Asm[buf][a_soff[i][j]] = f2tf32(vv[j]);
        }
        #pragma unroll
        for (int i = 0; i < 2; i++) {
            float vv[4] = {vb[i].x, vb[i].y, vb[i].z, vb[i].w};
            #pragma unroll
            for (int j = 0; j < 4; j++) Bsm[buf][b_soff[i][j]] = f2tf32(vv[j]);
        }
    };

    // ---- compute one 16-wide K tile out of smem buffer ----
    auto compute_tile = [&](int buf) {
        #pragma unroll
        for (int ks = 0; ks < 2; ks++) {
            uint32_t a[4][4];
            #pragma unroll
            for (int mt = 0; mt < 4; mt++) {
                const uint4 v4 = *reinterpret_cast<const uint4*>(
                    &Asm[buf][(((warp_m * 4 + mt) * 2 + ks) * 128) + lane * 4]);
                a[mt][0] = v4.x; a[mt][1] = v4.y; a[mt][2] = v4.z; a[mt][3] = v4.w;
            }
            uint32_t b[4][2];
            #pragma unroll
            for (int nt = 0; nt < 4; nt++) {
                const uint2 v2 = *reinterpret_cast<const uint2*>(
                    &Bsm[buf][(((warp_n * 4 + nt) * 2 + ks) * 64) + lane * 2]);
                b[nt][0] = v2.x; b[nt][1] = v2.y;
            }
            #pragma unroll
            for (int mt = 0; mt < 4; mt++)
                #pragma unroll
                for (int nt = 0; nt < 4; nt++)
                    mma_tf32(c[mt][nt][0], c[mt][nt][1], c[mt][nt][2], c[mt][nt][3],
                             a[mt][0], a[mt][1], a[mt][2], a[mt][3],
                             b[nt][0], b[nt][1]);
        }
    };

    // ---- pipelined mainloop ----
    load_tile(0);
    store_tile(0);
    __syncthreads();
    for (int kt = 0; kt < KT; ++kt) {
        const int cur = kt & 1;
        if (kt + 1 < KT) load_tile(kt + 1);   // prefetch next tile (latency hidden by compute)
        compute_tile(cur);
        if (kt + 1 < KT) {
            store_tile(cur ^ 1);              // other buffer: safe while peers compute cur
            __syncthreads();
        }
    }

    // ---- epilogue ----
    #pragma unroll
    for (int mt = 0; mt < 4; mt++) {
        int r0 = bm + warp_m * 64 + mt * 16 + g;
        int r1 = r0 + 8;
        #pragma unroll
        for (int nt = 0; nt < 4; nt++) {
            int col = bn + warp_n * 32 + nt * 8 + tid4 * 2;
            float bv0 = bias0[col], bv1 = bias0[col + 1];
            if (CHUNKS == 2) { bv0 += bias1[col]; bv1 += bias1[col + 1]; }
            if (r0 < M) {
                float* p = &C[(size_t)r0 * DIM + col];
                p[0] = c[mt][nt][0] + bv0; p[1] = c[mt][nt][1] + bv1;
            }
            if (r1 < M) {
                float* p = &C[(size_t)r1 * DIM + col];
                p[0] = c[mt][nt][2] + bv0; p[1] = c[mt][nt][3] + bv1;
            }
        }
    }
}

// ---------------- launch ----------------
static void run_sort_aggregate(const float* xsrc, const int* src, const int* dst, float* aggout)
{
    zero_deg_kernel<<<(N_NODE + 255) / 256, 256>>>();
    hist_kernel<<<(N_EDGE + 255) / 256, 256>>>(dst);
    scan_kernel<<<1, 1024>>>();
    scatter_kernel<<<(N_EDGE + 255) / 256, 256>>>(src, dst);
    aggregate_kernel<<<N_NODE, 256>>>(xsrc, aggout);
}

extern "C" void kernel_launch(void* const* d_in, const int* in_sizes, int n_in,
                              void* d_out, int out_size)
{
    const float* x_drug = (const float*)d_in[0];
    const float* x_prot = (const float*)d_in[1];
    const float* W_ddi  = (const float*)d_in[2];
    const float* b_ddi  = (const float*)d_in[3];
    const float* W_dpi  = (const float*)d_in[4];
    const float* b_dpi  = (const float*)d_in[5];
    const float* W_ppi  = (const float*)d_in[6];
    const float* b_ppi  = (const float*)d_in[7];
    const int* src_ddi  = (const int*)d_in[8];
    const int* dst_ddi  = (const int*)d_in[9];
    const int* src_dpi  = (const int*)d_in[10];
    const int* dst_dpi  = (const int*)d_in[11];
    const int* src_ppi  = (const int*)d_in[12];
    const int* dst_ppi  = (const int*)d_in[13];

    float* out_drug = (float*)d_out;
    float* out_prot = out_drug + (size_t)N_NODE * DIM;

    float* agg0; cudaGetSymbolAddress((void**)&agg0, g_agg0);
    float* agg1; cudaGetSymbolAddress((void**)&agg1, g_agg1);

    dim3 grid(DIM / 128, (N_NODE + 127) / 128);

    // drug <- ddi(drug): single-chunk GEMM
    run_sort_aggregate(x_drug, src_ddi, dst_ddi, agg0);
    gemm_tf32_pipe<1><<<grid, 256>>>(agg0, nullptr, W_ddi, nullptr,
                                     b_ddi, nullptr, out_drug, N_NODE);

    // prot <- dpi(drug) + ppi(prot): fused K=2048 GEMM over both chunks
    run_sort_aggregate(x_prot, src_ppi, dst_ppi, agg1);   // ppi first (agg1)
    run_sort_aggregate(x_drug, src_dpi, dst_dpi, agg0);   // dpi (agg0, reused)
    gemm_tf32_pipe<2><<<grid, 256>>>(agg0, agg1, W_dpi, W_ppi,
                                     b_dpi, b_ppi, out_prot, N_NODE);
}

// round 4
// speedup vs baseline: 3.0449x; 3.0449x over previous
#include <cuda_runtime.h>
#include <cuda_bf16.h>
#include <cstdint>

// Problem constants
#define N_NODE 40000
#define N_EDGE 320000
#define DIM    1024

// ---------------- device scratch (no cudaMalloc allowed) ----------------
__device__ int   g_deg[N_NODE];
__device__ int   g_offs[N_NODE + 1];
__device__ int   g_cursor[N_NODE];
__device__ int   g_sorted_src[N_EDGE];
__device__ float g_agg0[(size_t)N_NODE * DIM];
__device__ float g_agg1[(size_t)N_NODE * DIM];
__device__ float g_wt0[(size_t)DIM * DIM];   // W transposed [n][k] + tf32-rounded
__device__ float g_wt1[(size_t)DIM * DIM];

// ---------------- helpers ----------------
__device__ __forceinline__ uint32_t f2tf32(float x) {
    uint32_t r;
    asm("cvt.rna.tf32.f32 %0, %1;" : "=r"(r) : "f"(x));
    return r;
}

__device__ __forceinline__ uint32_t smem_to_u32(const void* smem_ptr) {
    uint32_t addr;
    asm("{ .reg .u64 tmp; cvta.to.shared.u64 tmp, %1; cvt.u32.u64 %0, tmp; }"
        : "=r"(addr) : "l"(smem_ptr));
    return addr;
}

__device__ __forceinline__ void cp_async16(uint32_t smem_addr, const void* gptr, uint32_t src_size) {
    asm volatile("cp.async.ca.shared.global [%0], [%1], 16, %2;"
                 :: "r"(smem_addr), "l"(gptr), "r"(src_size));
}
__device__ __forceinline__ void cp_async_commit() {
    asm volatile("cp.async.commit_group;" ::: "memory");
}
template <int N>
__device__ __forceinline__ void cp_async_wait() {
    asm volatile("cp.async.wait_group %0;" :: "n"(N) : "memory");
}

__device__ __forceinline__ void mma_tf32(float& c0, float& c1, float& c2, float& c3,
                                         uint32_t a0, uint32_t a1, uint32_t a2, uint32_t a3,
                                         uint32_t b0, uint32_t b1) {
    asm volatile(
        "mma.sync.aligned.m16n8k8.row.col.f32.tf32.tf32.f32 "
        "{%0,%1,%2,%3}, {%4,%5,%6,%7}, {%8,%9}, {%0,%1,%2,%3};"
        : "+f"(c0), "+f"(c1), "+f"(c2), "+f"(c3)
        : "r"(a0), "r"(a1), "r"(a2), "r"(a3), "r"(b0), "r"(b1));
}

// ---------------- sort-by-dst pipeline ----------------
__global__ void zero_deg_kernel() {
    int i = blockIdx.x * blockDim.x + threadIdx.x;
    if (i < N_NODE) g_deg[i] = 0;
}

__global__ void hist_kernel(const int* __restrict__ dst) {
    int i = blockIdx.x * blockDim.x + threadIdx.x;
    if (i < N_EDGE) atomicAdd(&g_deg[dst[i]], 1);
}

__global__ void scan_kernel() {
    __shared__ int sh[1024];
    __shared__ int carry;
    int t = threadIdx.x;
    if (t == 0) carry = 0;
    __syncthreads();
    for (int base = 0; base < N_NODE; base += 1024) {
        int idx = base + t;
        int v = (idx < N_NODE) ? g_deg[idx] : 0;
        sh[t] = v;
        __syncthreads();
        #pragma unroll
        for (int off = 1; off < 1024; off <<= 1) {
            int x = (t >= off) ? sh[t - off] : 0;
            __syncthreads();
            sh[t] += x;
            __syncthreads();
        }
        int incl = sh[t];
        int excl = incl - v;
        int c = carry;
        if (idx < N_NODE) {
            g_offs[idx]   = c + excl;
            g_cursor[idx] = c + excl;
        }
        int total = sh[1023];
        __syncthreads();
        if (t == 0) carry = c + total;
        __syncthreads();
    }
    if (t == 0) g_offs[N_NODE] = carry;
}

__global__ void scatter_kernel(const int* __restrict__ src, const int* __restrict__ dst) {
    int i = blockIdx.x * blockDim.x + threadIdx.x;
    if (i < N_EDGE) {
        int pos = atomicAdd(&g_cursor[dst[i]], 1);
        g_sorted_src[pos] = src[i];
    }
}

// one block per dst node; emits tf32(RNA)-rounded fp32 rows
__global__ void aggregate_kernel(const float* __restrict__ xsrc, float* __restrict__ aggout) {
    int v = blockIdx.x;
    int beg = g_offs[v];
    int end = g_offs[v + 1];
    int t = threadIdx.x;

    float4 acc = make_float4(0.f, 0.f, 0.f, 0.f);
    const float4* xs = reinterpret_cast<const float4*>(xsrc);
    int e = beg;
    for (; e + 1 < end; e += 2) {
        int s0 = g_sorted_src[e];
        int s1 = g_sorted_src[e + 1];
        float4 r0 = xs[(size_t)s0 * (DIM / 4) + t];
        float4 r1 = xs[(size_t)s1 * (DIM / 4) + t];
        acc.x += r0.x + r1.x; acc.y += r0.y + r1.y;
        acc.z += r0.z + r1.z; acc.w += r0.w + r1.w;
    }
    if (e < end) {
        int s = g_sorted_src[e];
        float4 r = xs[(size_t)s * (DIM / 4) + t];
        acc.x += r.x; acc.y += r.y; acc.z += r.z; acc.w += r.w;
    }
    int d = end - beg;
    float inv = 1.0f / (float)(d > 1 ? d : 1);
    float4 o;
    o.x = __uint_as_float(f2tf32(acc.x * inv));
    o.y = __uint_as_float(f2tf32(acc.y * inv));
    o.z = __uint_as_float(f2tf32(acc.z * inv));
    o.w = __uint_as_float(f2tf32(acc.w * inv));
    reinterpret_cast<float4*>(aggout)[(size_t)v * (DIM / 4) + t] = o;
}

// W[k][n] -> Wt[n][k], tf32(RNA)-rounded
__global__ void transpose_round_kernel(const float* __restrict__ W, float* __restrict__ Wt) {
    __shared__ float tile[32][33];
    int bx = blockIdx.x * 32, by = blockIdx.y * 32;
    int tx = threadIdx.x, ty = threadIdx.y;   // 32 x 8
    #pragma unroll
    for (int i = 0; i < 32; i += 8)
        tile[ty + i][tx] = W[(size_t)(by + ty + i) * DIM + bx + tx];
    __syncthreads();
    #pragma unroll
    for (int i = 0; i < 32; i += 8)
        Wt[(size_t)(bx + ty + i) * DIM + by + tx] = __uint_as_float(f2tf32(tile[tx][ty + i]));
}

// ---------------- cp.async-pipelined TF32 mma.sync GEMM ----------------
// C[M,1024] = sum_chunks A_c[M,1024] @ Wt_c[n][k]^T + bias
// BM=128 BN=128 BK=16, 3-stage cp.async pipeline, 256 threads (8 warps 2x4),
// padded smem rows (20 floats) -> conflict-free scalar LDS fragment loads.
#define LDR   20                         // floats per smem row (16 + 4 pad)
#define ATILE (128 * LDR)                // floats per A (or B) tile = 2560
#define STAGE_FLOATS (2 * ATILE)         // A + B per stage
#define NSTAGE 3
#define GEMM_SMEM_DYN (NSTAGE * STAGE_FLOATS * 4)   // 61440 B

template <int CHUNKS>
__global__ __launch_bounds__(256, 2) void gemm_tf32_cpasync(
    const float* __restrict__ A0, const float* __restrict__ A1,
    const float* __restrict__ Wt0, const float* __restrict__ Wt1,
    const float* __restrict__ bias0, const float* __restrict__ bias1,
    float* __restrict__ C, int M)
{
    extern __shared__ float smem[];
    const uint32_t smem_u32 = smem_to_u32(smem);

    const int t      = threadIdx.x;
    const int lane   = t & 31;
    const int warp   = t >> 5;
    const int warp_m = warp >> 2;   // 0..1
    const int warp_n = warp & 3;    // 0..3
    const int g      = lane >> 2;   // groupID 0..7
    const int tid4   = lane & 3;    // thread-in-group 0..3
    const int bm     = blockIdx.y * 128;
    const int bn     = blockIdx.x * 128;

    const int KT = 64 * CHUNKS;     // number of BK=16 tiles

    // staging indices: idx = t + i*256 -> row = idx>>2 (0..127), chunk = idx&3 (16B)
    const int s_row0 = t >> 2;
    const int s_row1 = (t + 256) >> 2;
    const int s_c    = t & 3;

    auto stage = [&](int kt, int buf) {
        const float* Asrc = (CHUNKS == 2 && kt >= 64) ? A1 : A0;
        const float* Bsrc = (CHUNKS == 2 && kt >= 64) ? Wt1 : Wt0;
        const int k0 = (kt & 63) * 16;
        const uint32_t abase = smem_u32 + (uint32_t)buf * (STAGE_FLOATS * 4);
        const uint32_t bbase = abase + ATILE * 4;
        #pragma unroll
        for (int i = 0; i < 2; i++) {
            int row = i ? s_row1 : s_row0;
            // A (guard M)
            int gm = bm + row;
            int gmc = (gm < M) ? gm : 0;
            cp_async16(abase + (uint32_t)(row * LDR + s_c * 4) * 4,
                       Asrc + (size_t)gmc * DIM + k0 + s_c * 4,
                       (gm < M) ? 16u : 0u);
            // B
            int gn = bn + row;
            cp_async16(bbase + (uint32_t)(row * LDR + s_c * 4) * 4,
                       Bsrc + (size_t)gn * DIM + k0 + s_c * 4, 16u);
        }
    };

    float c[4][4][4];
    #pragma unroll
    for (int mt = 0; mt < 4; mt++)
        #pragma unroll
        for (int nt = 0; nt < 4; nt++)
            #pragma unroll
            for (int r = 0; r < 4; r++) c[mt][nt][r] = 0.f;

    auto compute = [&](int buf) {
        const uint32_t* As = reinterpret_cast<const uint32_t*>(smem) + buf * STAGE_FLOATS;
        const uint32_t* Bs = As + ATILE;
        #pragma unroll
        for (int ks = 0; ks < 2; ks++) {
            const int kb = ks * 8;
            uint32_t a[4][4], b[4][2];
            #pragma unroll
            for (int mt = 0; mt < 4; mt++) {
                const uint32_t* ar0 = As + (warp_m * 64 + mt * 16 + g) * LDR + kb + tid4;
                const uint32_t* ar1 = ar0 + 8 * LDR;
                a[mt][0] = ar0[0]; a[mt][1] = ar1[0];
                a[mt][2] = ar0[4]; a[mt][3] = ar1[4];
            }
            #pragma unroll
            for (int nt = 0; nt < 4; nt++) {
                const uint32_t* br = Bs + (warp_n * 32 + nt * 8 + g) * LDR + kb + tid4;
                b[nt][0] = br[0]; b[nt][1] = br[4];
            }
            #pragma unroll
            for (int mt = 0; mt < 4; mt++)
                #pragma unroll
                for (int nt = 0; nt < 4; nt++)
                    mma_tf32(c[mt][nt][0], c[mt][nt][1], c[mt][nt][2], c[mt][nt][3],
                             a[mt][0], a[mt][1], a[mt][2], a[mt][3],
                             b[nt][0], b[nt][1]);
        }
    };

    // ---- prologue: fill 2 stages ----
    stage(0, 0); cp_async_commit();
    stage(1, 1); cp_async_commit();

    // ---- mainloop ----
    int buf = 0;
    for (int kt = 0; kt < KT; ++kt) {
        cp_async_wait<1>();          // stage kt complete (<=1 group pending)
        __syncthreads();             // visibility + guards buffer reuse
        compute(buf);
        if (kt + 2 < KT) stage(kt + 2, (buf + 2) % NSTAGE);
        cp_async_commit();           // keep group accounting uniform
        buf = (buf + 1) % NSTAGE;
    }

    // ---- epilogue ----
    #pragma unroll
    for (int mt = 0; mt < 4; mt++) {
        int r0 = bm + warp_m * 64 + mt * 16 + g;
        int r1 = r0 + 8;
        #pragma unroll
        for (int nt = 0; nt < 4; nt++) {
            int col = bn + warp_n * 32 + nt * 8 + tid4 * 2;
            float bv0 = bias0[col], bv1 = bias0[col + 1];
            if (CHUNKS == 2) { bv0 += bias1[col]; bv1 += bias1[col + 1]; }
            if (r0 < M) {
                float* p = &C[(size_t)r0 * DIM + col];
                p[0] = c[mt][nt][0] + bv0; p[1] = c[mt][nt][1] + bv1;
            }
            if (r1 < M) {
                float* p = &C[(size_t)r1 * DIM + col];
                p[0] = c[mt][nt][2] + bv0; p[1] = c[mt][nt][3] + bv1;
            }
        }
    }
}

// ---------------- launch ----------------
static void run_sort_aggregate(const float* xsrc, const int* src, const int* dst, float* aggout)
{
    zero_deg_kernel<<<(N_NODE + 255) / 256, 256>>>();
    hist_kernel<<<(N_EDGE + 255) / 256, 256>>>(dst);
    scan_kernel<<<1, 1024>>>();
    scatter_kernel<<<(N_EDGE + 255) / 256, 256>>>(src, dst);
    aggregate_kernel<<<N_NODE, 256>>>(xsrc, aggout);
}

extern "C" void kernel_launch(void* const* d_in, const int* in_sizes, int n_in,
                              void* d_out, int out_size)
{
    const float* x_drug = (const float*)d_in[0];
    const float* x_prot = (const float*)d_in[1];
    const float* W_ddi  = (const float*)d_in[2];
    const float* b_ddi  = (const float*)d_in[3];
    const float* W_dpi  = (const float*)d_in[4];
    const float* b_dpi  = (const float*)d_in[5];
    const float* W_ppi  = (const float*)d_in[6];
    const float* b_ppi  = (const float*)d_in[7];
    const int* src_ddi  = (const int*)d_in[8];
    const int* dst_ddi  = (const int*)d_in[9];
    const int* src_dpi  = (const int*)d_in[10];
    const int* dst_dpi  = (const int*)d_in[11];
    const int* src_ppi  = (const int*)d_in[12];
    const int* dst_ppi  = (const int*)d_in[13];

    float* out_drug = (float*)d_out;
    float* out_prot = out_drug + (size_t)N_NODE * DIM;

    float* agg0; cudaGetSymbolAddress((void**)&agg0, g_agg0);
    float* agg1; cudaGetSymbolAddress((void**)&agg1, g_agg1);
    float* wt0;  cudaGetSymbolAddress((void**)&wt0,  g_wt0);
    float* wt1;  cudaGetSymbolAddress((void**)&wt1,  g_wt1);

    cudaFuncSetAttribute(gemm_tf32_cpasync<1>,
                         cudaFuncAttributeMaxDynamicSharedMemorySize, GEMM_SMEM_DYN);
    cudaFuncSetAttribute(gemm_tf32_cpasync<2>,
                         cudaFuncAttributeMaxDynamicSharedMemorySize, GEMM_SMEM_DYN);

    dim3 tgrid(32, 32), tblk(32, 8);
    dim3 grid(DIM / 128, (N_NODE + 127) / 128);

    // drug <- ddi(drug)
    transpose_round_kernel<<<tgrid, tblk>>>(W_ddi, wt0);
    run_sort_aggregate(x_drug, src_ddi, dst_ddi, agg0);
    gemm_tf32_cpasync<1><<<grid, 256, GEMM_SMEM_DYN>>>(
        agg0, nullptr, wt0, nullptr, b_ddi, nullptr, out_drug, N_NODE);

    // prot <- dpi(drug) + ppi(prot): fused K=2048 GEMM
    run_sort_aggregate(x_prot, src_ppi, dst_ppi, agg1);
    run_sort_aggregate(x_drug, src_dpi, dst_dpi, agg0);
    transpose_round_kernel<<<tgrid, tblk>>>(W_dpi, wt0);
    transpose_round_kernel<<<tgrid, tblk>>>(W_ppi, wt1);
    gemm_tf32_cpasync<2><<<grid, 256, GEMM_SMEM_DYN>>>(
        agg0, agg1, wt0, wt1, b_dpi, b_ppi, out_prot, N_NODE);
}

// round 5
// speedup vs baseline: 3.2726x; 1.0748x over previous
#include <cuda_runtime.h>
#include <cuda_bf16.h>
#include <cstdint>

// Problem constants
#define N_NODE 40000
#define N_EDGE 320000
#define DIM    1024
#define NBLK_SCAN 40            // ceil(40000/1024)

// ---------------- device scratch (no cudaMalloc allowed) ----------------
__device__ int   g_deg[3 * N_NODE];
__device__ int   g_offs[3 * (N_NODE + 1)];
__device__ int   g_cursor[3 * N_NODE];
__device__ int   g_sorted_src[3 * N_EDGE];
__device__ int   g_bsum[3 * NBLK_SCAN];
__device__ int   g_boff[3 * NBLK_SCAN];
__device__ float g_agg0[(size_t)N_NODE * DIM];
__device__ float g_agg1[(size_t)N_NODE * DIM];
__device__ float g_agg2[(size_t)N_NODE * DIM];
__device__ float g_wt0[(size_t)DIM * DIM];
__device__ float g_wt1[(size_t)DIM * DIM];
__device__ float g_wt2[(size_t)DIM * DIM];

// ---------------- helpers ----------------
__device__ __forceinline__ uint32_t f2tf32(float x) {
    uint32_t r;
    asm("cvt.rna.tf32.f32 %0, %1;" : "=r"(r) : "f"(x));
    return r;
}

__device__ __forceinline__ uint32_t smem_to_u32(const void* smem_ptr) {
    uint32_t addr;
    asm("{ .reg .u64 tmp; cvta.to.shared.u64 tmp, %1; cvt.u32.u64 %0, tmp; }"
        : "=r"(addr) : "l"(smem_ptr));
    return addr;
}

__device__ __forceinline__ void cp_async16(uint32_t smem_addr, const void* gptr, uint32_t src_size) {
    asm volatile("cp.async.ca.shared.global [%0], [%1], 16, %2;"
                 :: "r"(smem_addr), "l"(gptr), "r"(src_size));
}
__device__ __forceinline__ void cp_async_commit() {
    asm volatile("cp.async.commit_group;" ::: "memory");
}
template <int N>
__device__ __forceinline__ void cp_async_wait() {
    asm volatile("cp.async.wait_group %0;" :: "n"(N) : "memory");
}

__device__ __forceinline__ void mma_tf32(float& c0, float& c1, float& c2, float& c3,
                                         uint32_t a0, uint32_t a1, uint32_t a2, uint32_t a3,
                                         uint32_t b0, uint32_t b1) {
    asm volatile(
        "mma.sync.aligned.m16n8k8.row.col.f32.tf32.tf32.f32 "
        "{%0,%1,%2,%3}, {%4,%5,%6,%7}, {%8,%9}, {%0,%1,%2,%3};"
        : "+f"(c0), "+f"(c1), "+f"(c2), "+f"(c3)
        : "r"(a0), "r"(a1), "r"(a2), "r"(a3), "r"(b0), "r"(b1));
}

// ---------------- sort-by-dst pipeline (per-relation scratch, rel = 0..2) ----------------
__global__ void zero_deg_kernel(int rel) {
    int i = blockIdx.x * blockDim.x + threadIdx.x;
    if (i < N_NODE) g_deg[rel * N_NODE + i] = 0;
}

__global__ void hist_kernel(int rel, const int* __restrict__ dst) {
    int i = blockIdx.x * blockDim.x + threadIdx.x;
    if (i < N_EDGE) atomicAdd(&g_deg[rel * N_NODE + dst[i]], 1);
}

// per-block exclusive scan (1024 elems/block) via warp shuffles; writes partial offs + block totals
__global__ void scan_block_kernel(int rel) {
    int t = threadIdx.x;
    int lane = t & 31, wid = t >> 5;
    int gidx = blockIdx.x * 1024 + t;
    int v = (gidx < N_NODE) ? g_deg[rel * N_NODE + gidx] : 0;
    int x = v;
    #pragma unroll
    for (int o = 1; o < 32; o <<= 1) {
        int y = __shfl_up_sync(0xFFFFFFFFu, x, o);
        if (lane >= o) x += y;
    }
    __shared__ int wsum[32];
    if (lane == 31) wsum[wid] = x;
    __syncthreads();
    if (wid == 0) {
        int w = wsum[lane];
        #pragma unroll
        for (int o = 1; o < 32; o <<= 1) {
            int y = __shfl_up_sync(0xFFFFFFFFu, w, o);
            if (lane >= o) w += y;
        }
        wsum[lane] = w;
    }
    __syncthreads();
    int incl = x + (wid ? wsum[wid - 1] : 0);
    if (gidx < N_NODE) g_offs[rel * (N_NODE + 1) + gidx] = incl - v;
    if (t == 0) g_bsum[rel * NBLK_SCAN + blockIdx.x] = 0;   // placeholder ordering safety
    __syncthreads();
    if (t == 1023) g_bsum[rel * NBLK_SCAN + blockIdx.x] = wsum[31];
}

// scan the 40 block sums (single tiny block)
__global__ void scan_sums_kernel(int rel) {
    if (threadIdx.x == 0) {
        int acc = 0;
        #pragma unroll
        for (int b = 0; b < NBLK_SCAN; ++b) {
            g_boff[rel * NBLK_SCAN + b] = acc;
            acc += g_bsum[rel * NBLK_SCAN + b];
        }
        g_offs[rel * (N_NODE + 1) + N_NODE] = acc;
    }
}

// add block offsets; produce final offs + cursor
__global__ void scan_add_kernel(int rel) {
    int gidx = blockIdx.x * 1024 + threadIdx.x;
    if (gidx < N_NODE) {
        int o = g_offs[rel * (N_NODE + 1) + gidx] + g_boff[rel * NBLK_SCAN + blockIdx.x];
        g_offs[rel * (N_NODE + 1) + gidx] = o;
        g_cursor[rel * N_NODE + gidx] = o;
    }
}

__global__ void scatter_kernel(int rel, const int* __restrict__ src, const int* __restrict__ dst) {
    int i = blockIdx.x * blockDim.x + threadIdx.x;
    if (i < N_EDGE) {
        int pos = atomicAdd(&g_cursor[rel * N_NODE + dst[i]], 1);
        g_sorted_src[rel * N_EDGE + pos] = src[i];
    }
}

// one block per dst node; emits tf32(RNA)-rounded fp32 rows
__global__ void aggregate_kernel(int rel, const float* __restrict__ xsrc, float* __restrict__ aggout) {
    int v = blockIdx.x;
    const int* offs = g_offs + rel * (N_NODE + 1);
    const int* srt  = g_sorted_src + rel * N_EDGE;
    int beg = offs[v];
    int end = offs[v + 1];
    int t = threadIdx.x;

    float4 acc = make_float4(0.f, 0.f, 0.f, 0.f);
    const float4* xs = reinterpret_cast<const float4*>(xsrc);
    int e = beg;
    for (; e + 3 < end; e += 4) {
        int s0 = srt[e], s1 = srt[e + 1], s2 = srt[e + 2], s3 = srt[e + 3];
        float4 r0 = xs[(size_t)s0 * (DIM / 4) + t];
        float4 r1 = xs[(size_t)s1 * (DIM / 4) + t];
        float4 r2 = xs[(size_t)s2 * (DIM / 4) + t];
        float4 r3 = xs[(size_t)s3 * (DIM / 4) + t];
        acc.x += (r0.x + r1.x) + (r2.x + r3.x);
        acc.y += (r0.y + r1.y) + (r2.y + r3.y);
        acc.z += (r0.z + r1.z) + (r2.z + r3.z);
        acc.w += (r0.w + r1.w) + (r2.w + r3.w);
    }
    for (; e < end; ++e) {
        int s = srt[e];
        float4 r = xs[(size_t)s * (DIM / 4) + t];
        acc.x += r.x; acc.y += r.y; acc.z += r.z; acc.w += r.w;
    }
    int d = end - beg;
    float inv = 1.0f / (float)(d > 1 ? d : 1);
    float4 o;
    o.x = __uint_as_float(f2tf32(acc.x * inv));
    o.y = __uint_as_float(f2tf32(acc.y * inv));
    o.z = __uint_as_float(f2tf32(acc.z * inv));
    o.w = __uint_as_float(f2tf32(acc.w * inv));
    reinterpret_cast<float4*>(aggout)[(size_t)v * (DIM / 4) + t] = o;
}

// W[k][n] -> Wt[n][k], tf32(RNA)-rounded
__global__ void transpose_round_kernel(const float* __restrict__ W, float* __restrict__ Wt) {
    __shared__ float tile[32][33];
    int bx = blockIdx.x * 32, by = blockIdx.y * 32;
    int tx = threadIdx.x, ty = threadIdx.y;   // 32 x 8
    #pragma unroll
    for (int i = 0; i < 32; i += 8)
        tile[ty + i][tx] = W[(size_t)(by + ty + i) * DIM + bx + tx];
    __syncthreads();
    #pragma unroll
    for (int i = 0; i < 32; i += 8)
        Wt[(size_t)(bx + ty + i) * DIM + by + tx] = __uint_as_float(f2tf32(tile[tx][ty + i]));
}

// ---------------- cp.async-pipelined TF32 mma.sync GEMM ----------------
// C[M,1024] (= or +=) A[M,1024] @ Wt[n][k]^T + bias
// BM=128 BN=128 BK=16, 3-stage cp.async pipeline, 256 threads (8 warps 2x4),
// padded smem rows (20 floats) -> conflict-free scalar LDS fragment loads.
#define LDR   20
#define ATILE (128 * LDR)
#define STAGE_FLOATS (2 * ATILE)
#define NSTAGE 3
#define GEMM_SMEM_DYN (NSTAGE * STAGE_FLOATS * 4)   // 61440 B

template <int ACCUM>
__global__ __launch_bounds__(256, 2) void gemm_tf32_cpasync(
    const float* __restrict__ A0, const float* __restrict__ Wt0,
    const float* __restrict__ bias0, float* __restrict__ C, int M)
{
    extern __shared__ float smem[];
    const uint32_t smem_u32 = smem_to_u32(smem);

    const int t      = threadIdx.x;
    const int lane   = t & 31;
    const int warp   = t >> 5;
    const int warp_m = warp >> 2;
    const int warp_n = warp & 3;
    const int g      = lane >> 2;
    const int tid4   = lane & 3;
    const int bm     = blockIdx.y * 128;
    const int bn     = blockIdx.x * 128;

    const int KT = 64;

    const int s_row0 = t >> 2;
    const int s_row1 = (t + 256) >> 2;
    const int s_c    = t & 3;

    auto stage = [&](int kt, int buf) {
        const int k0 = kt * 16;
        const uint32_t abase = smem_u32 + (uint32_t)buf * (STAGE_FLOATS * 4);
        const uint32_t bbase = abase + ATILE * 4;
        #pragma unroll
        for (int i = 0; i < 2; i++) {
            int row = i ? s_row1 : s_row0;
            int gm = bm + row;
            int gmc = (gm < M) ? gm : 0;
            cp_async16(abase + (uint32_t)(row * LDR + s_c * 4) * 4,
                       A0 + (size_t)gmc * DIM + k0 + s_c * 4,
                       (gm < M) ? 16u : 0u);
            int gn = bn + row;
            cp_async16(bbase + (uint32_t)(row * LDR + s_c * 4) * 4,
                       Wt0 + (size_t)gn * DIM + k0 + s_c * 4, 16u);
        }
    };

    float c[4][4][4];
    #pragma unroll
    for (int mt = 0; mt < 4; mt++)
        #pragma unroll
        for (int nt = 0; nt < 4; nt++)
            #pragma unroll
            for (int r = 0; r < 4; r++) c[mt][nt][r] = 0.f;

    auto compute = [&](int buf) {
        const uint32_t* As = reinterpret_cast<const uint32_t*>(smem) + buf * STAGE_FLOATS;
        const uint32_t* Bs = As + ATILE;
        #pragma unroll
        for (int ks = 0; ks < 2; ks++) {
            const int kb = ks * 8;
            uint32_t a[4][4], b[4][2];
            #pragma unroll
            for (int mt = 0; mt < 4; mt++) {
                const uint32_t* ar0 = As + (warp_m * 64 + mt * 16 + g) * LDR + kb + tid4;
                const uint32_t* ar1 = ar0 + 8 * LDR;
                a[mt][0] = ar0[0]; a[mt][1] = ar1[0];
                a[mt][2] = ar0[4]; a[mt][3] = ar1[4];
            }
            #pragma unroll
            for (int nt = 0; nt < 4; nt++) {
                const uint32_t* br = Bs + (warp_n * 32 + nt * 8 + g) * LDR + kb + tid4;
                b[nt][0] = br[0]; b[nt][1] = br[4];
            }
            #pragma unroll
            for (int mt = 0; mt < 4; mt++)
                #pragma unroll
                for (int nt = 0; nt < 4; nt++)
                    mma_tf32(c[mt][nt][0], c[mt][nt][1], c[mt][nt][2], c[mt][nt][3],
                             a[mt][0], a[mt][1], a[mt][2], a[mt][3],
                             b[nt][0], b[nt][1]);
        }
    };

    stage(0, 0); cp_async_commit();
    stage(1, 1); cp_async_commit();

    int buf = 0;
    for (int kt = 0; kt < KT; ++kt) {
        cp_async_wait<1>();
        __syncthreads();
        compute(buf);
        if (kt + 2 < KT) stage(kt + 2, (buf + 2) % NSTAGE);
        cp_async_commit();
        buf = (buf + 1) % NSTAGE;
    }

    #pragma unroll
    for (int mt = 0; mt < 4; mt++) {
        int r0 = bm + warp_m * 64 + mt * 16 + g;
        int r1 = r0 + 8;
        #pragma unroll
        for (int nt = 0; nt < 4; nt++) {
            int col = bn + warp_n * 32 + nt * 8 + tid4 * 2;
            float bv0 = bias0[col], bv1 = bias0[col + 1];
            if (r0 < M) {
                float* p = &C[(size_t)r0 * DIM + col];
                if (ACCUM) { p[0] += c[mt][nt][0] + bv0; p[1] += c[mt][nt][1] + bv1; }
                else       { p[0]  = c[mt][nt][0] + bv0; p[1]  = c[mt][nt][1] + bv1; }
            }
            if (r1 < M) {
                float* p = &C[(size_t)r1 * DIM + col];
                if (ACCUM) { p[0] += c[mt][nt][2] + bv0; p[1] += c[mt][nt][3] + bv1; }
                else       { p[0]  = c[mt][nt][2] + bv0; p[1]  = c[mt][nt][3] + bv1; }
            }
        }
    }
}

// ---------------- launch ----------------
static void run_sort_aggregate(cudaStream_t s, int rel, const float* xsrc,
                               const int* src, const int* dst, float* aggout)
{
    zero_deg_kernel<<<(N_NODE + 255) / 256, 256, 0, s>>>(rel);
    hist_kernel<<<(N_EDGE + 255) / 256, 256, 0, s>>>(rel, dst);
    scan_block_kernel<<<NBLK_SCAN, 1024, 0, s>>>(rel);
    scan_sums_kernel<<<1, 32, 0, s>>>(rel);
    scan_add_kernel<<<NBLK_SCAN, 1024, 0, s>>>(rel);
    scatter_kernel<<<(N_EDGE + 255) / 256, 256, 0, s>>>(rel, src, dst);
    aggregate_kernel<<<N_NODE, 256, 0, s>>>(rel, xsrc, aggout);
}

extern "C" void kernel_launch(void* const* d_in, const int* in_sizes, int n_in,
                              void* d_out, int out_size)
{
    const float* x_drug = (const float*)d_in[0];
    const float* x_prot = (const float*)d_in[1];
    const float* W_ddi  = (const float*)d_in[2];
    const float* b_ddi  = (const float*)d_in[3];
    const float* W_dpi  = (const float*)d_in[4];
    const float* b_dpi  = (const float*)d_in[5];
    const float* W_ppi  = (const float*)d_in[6];
    const float* b_ppi  = (const float*)d_in[7];
    const int* src_ddi  = (const int*)d_in[8];
    const int* dst_ddi  = (const int*)d_in[9];
    const int* src_dpi  = (const int*)d_in[10];
    const int* dst_dpi  = (const int*)d_in[11];
    const int* src_ppi  = (const int*)d_in[12];
    const int* dst_ppi  = (const int*)d_in[13];

    float* out_drug = (float*)d_out;
    float* out_prot = out_drug + (size_t)N_NODE * DIM;

    float* agg0; cudaGetSymbolAddress((void**)&agg0, g_agg0);
    float* agg1; cudaGetSymbolAddress((void**)&agg1, g_agg1);
    float* agg2; cudaGetSymbolAddress((void**)&agg2, g_agg2);
    float* wt0;  cudaGetSymbolAddress((void**)&wt0,  g_wt0);
    float* wt1;  cudaGetSymbolAddress((void**)&wt1,  g_wt1);
    float* wt2;  cudaGetSymbolAddress((void**)&wt2,  g_wt2);

    cudaFuncSetAttribute(gemm_tf32_cpasync<0>,
                         cudaFuncAttributeMaxDynamicSharedMemorySize, GEMM_SMEM_DYN);
    cudaFuncSetAttribute(gemm_tf32_cpasync<1>,
                         cudaFuncAttributeMaxDynamicSharedMemorySize, GEMM_SMEM_DYN);

    dim3 tgrid(32, 32), tblk(32, 8);
    dim3 grid(DIM / 128, (N_NODE + 127) / 128);

    // fork a side stream off the capture (default) stream
    cudaStream_t s1;
    cudaStreamCreateWithFlags(&s1, cudaStreamNonBlocking);
    cudaEvent_t evF, evPpi, evJ;
    cudaEventCreateWithFlags(&evF,   cudaEventDisableTiming);
    cudaEventCreateWithFlags(&evPpi, cudaEventDisableTiming);
    cudaEventCreateWithFlags(&evJ,   cudaEventDisableTiming);

    cudaEventRecord(evF, 0);
    cudaStreamWaitEvent(s1, evF, 0);

    // ---- side stream: ppi aggregate, then full ddi relation ----
    transpose_round_kernel<<<tgrid, tblk, 0, s1>>>(W_ppi, wt1);
    run_sort_aggregate(s1, 1, x_prot, src_ppi, dst_ppi, agg1);
    cudaEventRecord(evPpi, s1);
    transpose_round_kernel<<<tgrid, tblk, 0, s1>>>(W_ddi, wt2);
    run_sort_aggregate(s1, 2, x_drug, src_ddi, dst_ddi, agg2);
    gemm_tf32_cpasync<0><<<grid, 256, GEMM_SMEM_DYN, s1>>>(agg2, wt2, b_ddi, out_drug, N_NODE);
    cudaEventRecord(evJ, s1);

    // ---- main stream: dpi relation, then ppi GEMM accumulate ----
    transpose_round_kernel<<<tgrid, tblk>>>(W_dpi, wt0);
    run_sort_aggregate(0, 0, x_drug, src_dpi, dst_dpi, agg0);
    gemm_tf32_cpasync<0><<<grid, 256, GEMM_SMEM_DYN>>>(agg0, wt0, b_dpi, out_prot, N_NODE);
    cudaStreamWaitEvent(0, evPpi, 0);
    gemm_tf32_cpasync<1><<<grid, 256, GEMM_SMEM_DYN>>>(agg1, wt1, b_ppi, out_prot, N_NODE);
    cudaStreamWaitEvent(0, evJ, 0);
}

// round 8
// speedup vs baseline: 3.2920x; 1.0059x over previous
#include <cuda_runtime.h>
#include <cuda_bf16.h>
#include <cstdint>

// Problem constants
#define N_NODE 40000
#define N_EDGE 320000
#define DIM    1024
#define NBLK_SCAN 40            // ceil(40000/1024)
#define DCHUNKS 4               // 4 x 256-float slices (40MB L2-resident working set each)

// ---------------- device scratch (no cudaMalloc allowed) ----------------
__device__ int   g_deg[3 * N_NODE];
__device__ int   g_offs[3 * (N_NODE + 1)];
__device__ int   g_cursor[3 * N_NODE];
__device__ int   g_sorted_src[3 * N_EDGE];
__device__ int   g_bsum[3 * NBLK_SCAN];
__device__ int   g_boff[3 * NBLK_SCAN];
__device__ float g_agg0[(size_t)N_NODE * DIM];
__device__ float g_wt0[(size_t)DIM * DIM];

// ---------------- helpers ----------------
__device__ __forceinline__ uint32_t f2tf32(float x) {
    uint32_t r;
    asm("cvt.rna.tf32.f32 %0, %1;" : "=r"(r) : "f"(x));
    return r;
}

__device__ __forceinline__ uint32_t smem_to_u32(const void* smem_ptr) {
    uint32_t addr;
    asm("{ .reg .u64 tmp; cvta.to.shared.u64 tmp, %1; cvt.u32.u64 %0, tmp; }"
        : "=r"(addr) : "l"(smem_ptr));
    return addr;
}

__device__ __forceinline__ void cp_async16(uint32_t smem_addr, const void* gptr, uint32_t src_size) {
    asm volatile("cp.async.ca.shared.global [%0], [%1], 16, %2;"
                 :: "r"(smem_addr), "l"(gptr), "r"(src_size));
}
__device__ __forceinline__ void cp_async_commit() {
    asm volatile("cp.async.commit_group;" ::: "memory");
}
template <int N>
__device__ __forceinline__ void cp_async_wait() {
    asm volatile("cp.async.wait_group %0;" :: "n"(N) : "memory");
}

__device__ __forceinline__ void mma_tf32(float& c0, float& c1, float& c2, float& c3,
                                         uint32_t a0, uint32_t a1, uint32_t a2, uint32_t a3,
                                         uint32_t b0, uint32_t b1) {
    asm volatile(
        "mma.sync.aligned.m16n8k8.row.col.f32.tf32.tf32.f32 "
        "{%0,%1,%2,%3}, {%4,%5,%6,%7}, {%8,%9}, {%0,%1,%2,%3};"
        : "+f"(c0), "+f"(c1), "+f"(c2), "+f"(c3)
        : "r"(a0), "r"(a1), "r"(a2), "r"(a3), "r"(b0), "r"(b1));
}

// ---------------- sort-by-dst pipeline (per-relation scratch, rel = 0..2) ----------------
__global__ void zero_deg_kernel(int rel) {
    int i = blockIdx.x * blockDim.x + threadIdx.x;
    if (i < N_NODE) g_deg[rel * N_NODE + i] = 0;
}

__global__ void hist_kernel(int rel, const int* __restrict__ dst) {
    int i = blockIdx.x * blockDim.x + threadIdx.x;
    if (i < N_EDGE) atomicAdd(&g_deg[rel * N_NODE + dst[i]], 1);
}

__global__ void scan_block_kernel(int rel) {
    int t = threadIdx.x;
    int lane = t & 31, wid = t >> 5;
    int gidx = blockIdx.x * 1024 + t;
    int v = (gidx < N_NODE) ? g_deg[rel * N_NODE + gidx] : 0;
    int x = v;
    #pragma unroll
    for (int o = 1; o < 32; o <<= 1) {
        int y = __shfl_up_sync(0xFFFFFFFFu, x, o);
        if (lane >= o) x += y;
    }
    __shared__ int wsum[32];
    if (lane == 31) wsum[wid] = x;
    __syncthreads();
    if (wid == 0) {
        int w = wsum[lane];
        #pragma unroll
        for (int o = 1; o < 32; o <<= 1) {
            int y = __shfl_up_sync(0xFFFFFFFFu, w, o);
            if (lane >= o) w += y;
        }
        wsum[lane] = w;
    }
    __syncthreads();
    int incl = x + (wid ? wsum[wid - 1] : 0);
    if (gidx < N_NODE) g_offs[rel * (N_NODE + 1) + gidx] = incl - v;
    __syncthreads();
    if (t == 1023) g_bsum[rel * NBLK_SCAN + blockIdx.x] = wsum[31];
}

__global__ void scan_sums_kernel(int rel) {
    if (threadIdx.x == 0) {
        int acc = 0;
        #pragma unroll
        for (int b = 0; b < NBLK_SCAN; ++b) {
            g_boff[rel * NBLK_SCAN + b] = acc;
            acc += g_bsum[rel * NBLK_SCAN + b];
        }
        g_offs[rel * (N_NODE + 1) + N_NODE] = acc;
    }
}

__global__ void scan_add_kernel(int rel) {
    int gidx = blockIdx.x * 1024 + threadIdx.x;
    if (gidx < N_NODE) {
        int o = g_offs[rel * (N_NODE + 1) + gidx] + g_boff[rel * NBLK_SCAN + blockIdx.x];
        g_offs[rel * (N_NODE + 1) + gidx] = o;
        g_cursor[rel * N_NODE + gidx] = o;
    }
}

__global__ void scatter_kernel(int rel, const int* __restrict__ src, const int* __restrict__ dst) {
    int i = blockIdx.x * blockDim.x + threadIdx.x;
    if (i < N_EDGE) {
        int pos = atomicAdd(&g_cursor[rel * N_NODE + dst[i]], 1);
        g_sorted_src[rel * N_EDGE + pos] = src[i];
    }
}

// D-chunked aggregate: one block (64 threads) per dst node, one 256-float slice.
// Sequential passes over dchunk keep the gathered slice (40MB) L2-resident.
__global__ void aggregate_chunk_kernel(int rel, int dchunk,
                                       const float* __restrict__ xsrc,
                                       float* __restrict__ aggout) {
    int v = blockIdx.x;
    const int* offs = g_offs + rel * (N_NODE + 1);
    const int* srt  = g_sorted_src + rel * N_EDGE;
    int beg = offs[v];
    int end = offs[v + 1];
    int t = threadIdx.x;                       // 0..63
    const int qoff = dchunk * 64 + t;          // float4 index within the row

    float4 acc = make_float4(0.f, 0.f, 0.f, 0.f);
    const float4* xs = reinterpret_cast<const float4*>(xsrc);
    int e = beg;
    for (; e + 7 < end; e += 8) {
        float4 r[8];
        #pragma unroll
        for (int j = 0; j < 8; j++)
            r[j] = xs[(size_t)srt[e + j] * (DIM / 4) + qoff];
        #pragma unroll
        for (int j = 0; j < 8; j++) {
            acc.x += r[j].x; acc.y += r[j].y; acc.z += r[j].z; acc.w += r[j].w;
        }
    }
    for (; e + 1 < end; e += 2) {
        float4 r0 = xs[(size_t)srt[e] * (DIM / 4) + qoff];
        float4 r1 = xs[(size_t)srt[e + 1] * (DIM / 4) + qoff];
        acc.x += r0.x + r1.x; acc.y += r0.y + r1.y;
        acc.z += r0.z + r1.z; acc.w += r0.w + r1.w;
    }
    if (e < end) {
        float4 r = xs[(size_t)srt[e] * (DIM / 4) + qoff];
        acc.x += r.x; acc.y += r.y; acc.z += r.z; acc.w += r.w;
    }
    int d = end - beg;
    float inv = 1.0f / (float)(d > 1 ? d : 1);
    float4 o;
    o.x = __uint_as_float(f2tf32(acc.x * inv));
    o.y = __uint_as_float(f2tf32(acc.y * inv));
    o.z = __uint_as_float(f2tf32(acc.z * inv));
    o.w = __uint_as_float(f2tf32(acc.w * inv));
    reinterpret_cast<float4*>(aggout)[(size_t)v * (DIM / 4) + qoff] = o;
}

// W[k][n] -> Wt[n][k], tf32(RNA)-rounded
__global__ void transpose_round_kernel(const float* __restrict__ W, float* __restrict__ Wt) {
    __shared__ float tile[32][33];
    int bx = blockIdx.x * 32, by = blockIdx.y * 32;
    int tx = threadIdx.x, ty = threadIdx.y;   // 32 x 8
    #pragma unroll
    for (int i = 0; i < 32; i += 8)
        tile[ty + i][tx] = W[(size_t)(by + ty + i) * DIM + bx + tx];
    __syncthreads();
    #pragma unroll
    for (int i = 0; i < 32; i += 8)
        Wt[(size_t)(bx + ty + i) * DIM + by + tx] = __uint_as_float(f2tf32(tile[tx][ty + i]));
}

// ---------------- cp.async-pipelined TF32 mma.sync GEMM ----------------
// C[M,1024] (= or +=) A[M,1024] @ Wt[n][k]^T + bias
#define LDR   20
#define ATILE (128 * LDR)
#define STAGE_FLOATS (2 * ATILE)
#define NSTAGE 3
#define GEMM_SMEM_DYN (NSTAGE * STAGE_FLOATS * 4)   // 61440 B

template <int ACCUM>
__global__ __launch_bounds__(256, 2) void gemm_tf32_cpasync(
    const float* __restrict__ A0, const float* __restrict__ Wt0,
    const float* __restrict__ bias0, float* __restrict__ C, int M)
{
    extern __shared__ float smem[];
    const uint32_t smem_u32 = smem_to_u32(smem);

    const int t      = threadIdx.x;
    const int lane   = t & 31;
    const int warp   = t >> 5;
    const int warp_m = warp >> 2;
    const int warp_n = warp & 3;
    const int g      = lane >> 2;
    const int tid4   = lane & 3;
    const int bm     = blockIdx.y * 128;
    const int bn     = blockIdx.x * 128;

    const int KT = 64;

    const int s_row0 = t >> 2;
    const int s_row1 = (t + 256) >> 2;
    const int s_c    = t & 3;

    auto stage = [&](int kt, int buf) {
        const int k0 = kt * 16;
        const uint32_t abase = smem_u32 + (uint32_t)buf * (STAGE_FLOATS * 4);
        const uint32_t bbase = abase + ATILE * 4;
        #pragma unroll
        for (int i = 0; i < 2; i++) {
            int row = i ? s_row1 : s_row0;
            int gm = bm + row;
            int gmc = (gm < M) ? gm : 0;
            cp_async16(abase + (uint32_t)(row * LDR + s_c * 4) * 4,
                       A0 + (size_t)gmc * DIM + k0 + s_c * 4,
                       (gm < M) ? 16u : 0u);
            int gn = bn + row;
            cp_async16(bbase + (uint32_t)(row * LDR + s_c * 4) * 4,
                       Wt0 + (size_t)gn * DIM + k0 + s_c * 4, 16u);
        }
    };

    float c[4][4][4];
    #pragma unroll
    for (int mt = 0; mt < 4; mt++)
        #pragma unroll
        for (int nt = 0; nt < 4; nt++)
            #pragma unroll
            for (int r = 0; r < 4; r++) c[mt][nt][r] = 0.f;

    auto compute = [&](int buf) {
        const uint32_t* As = reinterpret_cast<const uint32_t*>(smem) + buf * STAGE_FLOATS;
        const uint32_t* Bs = As + ATILE;
        #pragma unroll
        for (int ks = 0; ks < 2; ks++) {
            const int kb = ks * 8;
            uint32_t a[4][4], b[4][2];
            #pragma unroll
            for (int mt = 0; mt < 4; mt++) {
                const uint32_t* ar0 = As + (warp_m * 64 + mt * 16 + g) * LDR + kb + tid4;
                const uint32_t* ar1 = ar0 + 8 * LDR;
                a[mt][0] = ar0[0]; a[mt][1] = ar1[0];
                a[mt][2] = ar0[4]; a[mt][3] = ar1[4];
            }
            #pragma unroll
            for (int nt = 0; nt < 4; nt++) {
                const uint32_t* br = Bs + (warp_n * 32 + nt * 8 + g) * LDR + kb + tid4;
                b[nt][0] = br[0]; b[nt][1] = br[4];
            }
            #pragma unroll
            for (int mt = 0; mt < 4; mt++)
                #pragma unroll
                for (int nt = 0; nt < 4; nt++)
                    mma_tf32(c[mt][nt][0], c[mt][nt][1], c[mt][nt][2], c[mt][nt][3],
                             a[mt][0], a[mt][1], a[mt][2], a[mt][3],
                             b[nt][0], b[nt][1]);
        }
    };

    stage(0, 0); cp_async_commit();
    stage(1, 1); cp_async_commit();

    int buf = 0;
    for (int kt = 0; kt < KT; ++kt) {
        cp_async_wait<1>();
        __syncthreads();
        compute(buf);
        if (kt + 2 < KT) stage(kt + 2, (buf + 2) % NSTAGE);
        cp_async_commit();
        buf = (buf + 1) % NSTAGE;
    }

    #pragma unroll
    for (int mt = 0; mt < 4; mt++) {
        int r0 = bm + warp_m * 64 + mt * 16 + g;
        int r1 = r0 + 8;
        #pragma unroll
        for (int nt = 0; nt < 4; nt++) {
            int col = bn + warp_n * 32 + nt * 8 + tid4 * 2;
            float bv0 = bias0[col], bv1 = bias0[col + 1];
            if (r0 < M) {
                float* p = &C[(size_t)r0 * DIM + col];
                if (ACCUM) { p[0] += c[mt][nt][0] + bv0; p[1] += c[mt][nt][1] + bv1; }
                else       { p[0]  = c[mt][nt][0] + bv0; p[1]  = c[mt][nt][1] + bv1; }
            }
            if (r1 < M) {
                float* p = &C[(size_t)r1 * DIM + col];
                if (ACCUM) { p[0] += c[mt][nt][2] + bv0; p[1] += c[mt][nt][3] + bv1; }
                else       { p[0]  = c[mt][nt][2] + bv0; p[1]  = c[mt][nt][3] + bv1; }
            }
        }
    }
}

// ---------------- launch (single capture stream, no stream/event objects) ----------------
static void run_sort(int rel, const int* src, const int* dst)
{
    zero_deg_kernel<<<(N_NODE + 255) / 256, 256>>>(rel);
    hist_kernel<<<(N_EDGE + 255) / 256, 256>>>(rel, dst);
    scan_block_kernel<<<NBLK_SCAN, 1024>>>(rel);
    scan_sums_kernel<<<1, 32>>>(rel);
    scan_add_kernel<<<NBLK_SCAN, 1024>>>(rel);
    scatter_kernel<<<(N_EDGE + 255) / 256, 256>>>(rel, src, dst);
}

static void run_aggregate(int rel, const float* xsrc, float* aggout)
{
    for (int c = 0; c < DCHUNKS; ++c)
        aggregate_chunk_kernel<<<N_NODE, 64>>>(rel, c, xsrc, aggout);
}

extern "C" void kernel_launch(void* const* d_in, const int* in_sizes, int n_in,
                              void* d_out, int out_size)
{
    const float* x_drug = (const float*)d_in[0];
    const float* x_prot = (const float*)d_in[1];
    const float* W_ddi  = (const float*)d_in[2];
    const float* b_ddi  = (const float*)d_in[3];
    const float* W_dpi  = (const float*)d_in[4];
    const float* b_dpi  = (const float*)d_in[5];
    const float* W_ppi  = (const float*)d_in[6];
    const float* b_ppi  = (const float*)d_in[7];
    const int* src_ddi  = (const int*)d_in[8];
    const int* dst_ddi  = (const int*)d_in[9];
    const int* src_dpi  = (const int*)d_in[10];
    const int* dst_dpi  = (const int*)d_in[11];
    const int* src_ppi  = (const int*)d_in[12];
    const int* dst_ppi  = (const int*)d_in[13];

    float* out_drug = (float*)d_out;
    float* out_prot = out_drug + (size_t)N_NODE * DIM;

    float* agg0; cudaGetSymbolAddress((void**)&agg0, g_agg0);
    float* wt0;  cudaGetSymbolAddress((void**)&wt0,  g_wt0);

    cudaFuncSetAttribute(gemm_tf32_cpasync<0>,
                         cudaFuncAttributeMaxDynamicSharedMemorySize, GEMM_SMEM_DYN);
    cudaFuncSetAttribute(gemm_tf32_cpasync<1>,
                         cudaFuncAttributeMaxDynamicSharedMemorySize, GEMM_SMEM_DYN);

    dim3 tgrid(32, 32), tblk(32, 8);
    dim3 grid(DIM / 128, (N_NODE + 127) / 128);

    // ---- dpi: prot = dpi(drug) ----
    run_sort(0, src_dpi, dst_dpi);
    transpose_round_kernel<<<tgrid, tblk>>>(W_dpi, wt0);
    run_aggregate(0, x_drug, agg0);
    gemm_tf32_cpasync<0><<<grid, 256, GEMM_SMEM_DYN>>>(agg0, wt0, b_dpi, out_prot, N_NODE);

    // ---- ppi: prot += ppi(prot) ----
    run_sort(1, src_ppi, dst_ppi);
    transpose_round_kernel<<<tgrid, tblk>>>(W_ppi, wt0);
    run_aggregate(1, x_prot, agg0);
    gemm_tf32_cpasync<1><<<grid, 256, GEMM_SMEM_DYN>>>(agg0, wt0, b_ppi, out_prot, N_NODE);

    // ---- ddi: drug = ddi(drug) ----
    run_sort(2, src_ddi, dst_ddi);
    transpose_round_kernel<<<tgrid, tblk>>>(W_ddi, wt0);
    run_aggregate(2, x_drug, agg0);
    gemm_tf32_cpasync<0><<<grid, 256, GEMM_SMEM_DYN>>>(agg0, wt0, b_ddi, out_drug, N_NODE);
}

// round 9
// speedup vs baseline: 3.4034x; 1.0338x over previous
#include <cuda_runtime.h>
#include <cuda_bf16.h>
#include <cstdint>

// Problem constants
#define N_NODE 40000
#define N_EDGE 320000
#define DIM    1024
#define NBLK_SCAN 40            // ceil(40000/1024)
#define DCHUNKS 4               // 4 x 256-float slices

// ---------------- device scratch (no cudaMalloc allowed) ----------------
__device__ int   g_deg[3 * N_NODE];
__device__ int   g_offs[3 * (N_NODE + 1)];
__device__ int   g_cursor[3 * N_NODE];
__device__ int   g_sorted_src[3 * N_EDGE];
__device__ int   g_bsum[3 * NBLK_SCAN];
__device__ float g_agg0[(size_t)N_NODE * DIM];   // dpi
__device__ float g_agg1[(size_t)N_NODE * DIM];   // ppi
__device__ float g_agg2[(size_t)N_NODE * DIM];   // ddi
__device__ float g_wt0[(size_t)DIM * DIM];
__device__ float g_wt1[(size_t)DIM * DIM];
__device__ float g_wt2[(size_t)DIM * DIM];

// ---------------- helpers ----------------
__device__ __forceinline__ uint32_t f2tf32(float x) {
    uint32_t r;
    asm("cvt.rna.tf32.f32 %0, %1;" : "=r"(r) : "f"(x));
    return r;
}

__device__ __forceinline__ uint32_t smem_to_u32(const void* smem_ptr) {
    uint32_t addr;
    asm("{ .reg .u64 tmp; cvta.to.shared.u64 tmp, %1; cvt.u32.u64 %0, tmp; }"
        : "=r"(addr) : "l"(smem_ptr));
    return addr;
}

__device__ __forceinline__ void cp_async16(uint32_t smem_addr, const void* gptr, uint32_t src_size) {
    asm volatile("cp.async.ca.shared.global [%0], [%1], 16, %2;"
                 :: "r"(smem_addr), "l"(gptr), "r"(src_size));
}
__device__ __forceinline__ void cp_async_commit() {
    asm volatile("cp.async.commit_group;" ::: "memory");
}
template <int N>
__device__ __forceinline__ void cp_async_wait() {
    asm volatile("cp.async.wait_group %0;" :: "n"(N) : "memory");
}

__device__ __forceinline__ void mma_tf32(float& c0, float& c1, float& c2, float& c3,
                                         uint32_t a0, uint32_t a1, uint32_t a2, uint32_t a3,
                                         uint32_t b0, uint32_t b1) {
    asm volatile(
        "mma.sync.aligned.m16n8k8.row.col.f32.tf32.tf32.f32 "
        "{%0,%1,%2,%3}, {%4,%5,%6,%7}, {%8,%9}, {%0,%1,%2,%3};"
        : "+f"(c0), "+f"(c1), "+f"(c2), "+f"(c3)
        : "r"(a0), "r"(a1), "r"(a2), "r"(a3), "r"(b0), "r"(b1));
}

// ---------------- sort-by-dst pipeline (per-relation scratch, rel = 0..2) ----------------
__global__ void zero_deg_kernel(int rel) {
    int i = blockIdx.x * blockDim.x + threadIdx.x;
    if (i < N_NODE) g_deg[rel * N_NODE + i] = 0;
}

__global__ void hist_kernel(int rel, const int* __restrict__ dst) {
    int i = blockIdx.x * blockDim.x + threadIdx.x;
    if (i < N_EDGE) atomicAdd(&g_deg[rel * N_NODE + dst[i]], 1);
}

__global__ void scan_block_kernel(int rel) {
    int t = threadIdx.x;
    int lane = t & 31, wid = t >> 5;
    int gidx = blockIdx.x * 1024 + t;
    int v = (gidx < N_NODE) ? g_deg[rel * N_NODE + gidx] : 0;
    int x = v;
    #pragma unroll
    for (int o = 1; o < 32; o <<= 1) {
        int y = __shfl_up_sync(0xFFFFFFFFu, x, o);
        if (lane >= o) x += y;
    }
    __shared__ int wsum[32];
    if (lane == 31) wsum[wid] = x;
    __syncthreads();
    if (wid == 0) {
        int w = wsum[lane];
        #pragma unroll
        for (int o = 1; o < 32; o <<= 1) {
            int y = __shfl_up_sync(0xFFFFFFFFu, w, o);
            if (lane >= o) w += y;
        }
        wsum[lane] = w;
    }
    __syncthreads();
    int incl = x + (wid ? wsum[wid - 1] : 0);
    if (gidx < N_NODE) g_offs[rel * (N_NODE + 1) + gidx] = incl - v;
    __syncthreads();
    if (t == 1023) g_bsum[rel * NBLK_SCAN + blockIdx.x] = wsum[31];
}

// fused: block-offset prefix computed in-block from g_bsum; writes final offs + cursor
__global__ void scan_add_kernel(int rel) {
    __shared__ int sh[NBLK_SCAN];
    int t = threadIdx.x;
    if (t < NBLK_SCAN) sh[t] = g_bsum[rel * NBLK_SCAN + t];
    __syncthreads();
    int boff = 0;
    for (int b = 0; b < blockIdx.x; ++b) boff += sh[b];   // uniform per block
    int gidx = blockIdx.x * 1024 + t;
    if (gidx < N_NODE) {
        int o = g_offs[rel * (N_NODE + 1) + gidx] + boff;
        g_offs[rel * (N_NODE + 1) + gidx] = o;
        g_cursor[rel * N_NODE + gidx] = o;
    }
    if (blockIdx.x == 0 && t == 0)
        g_offs[rel * (N_NODE + 1) + N_NODE] = N_EDGE;     // total is a constant
}

__global__ void scatter_kernel(int rel, const int* __restrict__ src, const int* __restrict__ dst) {
    int i = blockIdx.x * blockDim.x + threadIdx.x;
    if (i < N_EDGE) {
        int pos = atomicAdd(&g_cursor[rel * N_NODE + dst[i]], 1);
        g_sorted_src[rel * N_EDGE + pos] = src[i];
    }
}

// D-chunked aggregate: one block (64 threads) per dst node, one 256-float slice.
__global__ void aggregate_chunk_kernel(int rel, int dchunk,
                                       const float* __restrict__ xsrc,
                                       float* __restrict__ aggout) {
    int v = blockIdx.x;
    const int* offs = g_offs + rel * (N_NODE + 1);
    const int* srt  = g_sorted_src + rel * N_EDGE;
    int beg = offs[v];
    int end = offs[v + 1];
    int t = threadIdx.x;                       // 0..63
    const int qoff = dchunk * 64 + t;          // float4 index within the row

    float4 acc = make_float4(0.f, 0.f, 0.f, 0.f);
    const float4* xs = reinterpret_cast<const float4*>(xsrc);
    int e = beg;
    for (; e + 7 < end; e += 8) {
        float4 r[8];
        #pragma unroll
        for (int j = 0; j < 8; j++)
            r[j] = xs[(size_t)srt[e + j] * (DIM / 4) + qoff];
        #pragma unroll
        for (int j = 0; j < 8; j++) {
            acc.x += r[j].x; acc.y += r[j].y; acc.z += r[j].z; acc.w += r[j].w;
        }
    }
    for (; e + 1 < end; e += 2) {
        float4 r0 = xs[(size_t)srt[e] * (DIM / 4) + qoff];
        float4 r1 = xs[(size_t)srt[e + 1] * (DIM / 4) + qoff];
        acc.x += r0.x + r1.x; acc.y += r0.y + r1.y;
        acc.z += r0.z + r1.z; acc.w += r0.w + r1.w;
    }
    if (e < end) {
        float4 r = xs[(size_t)srt[e] * (DIM / 4) + qoff];
        acc.x += r.x; acc.y += r.y; acc.z += r.z; acc.w += r.w;
    }
    int d = end - beg;
    float inv = 1.0f / (float)(d > 1 ? d : 1);
    float4 o;
    o.x = __uint_as_float(f2tf32(acc.x * inv));
    o.y = __uint_as_float(f2tf32(acc.y * inv));
    o.z = __uint_as_float(f2tf32(acc.z * inv));
    o.w = __uint_as_float(f2tf32(acc.w * inv));
    reinterpret_cast<float4*>(aggout)[(size_t)v * (DIM / 4) + qoff] = o;
}

// W[k][n] -> Wt[n][k], tf32(RNA)-rounded
__global__ void transpose_round_kernel(const float* __restrict__ W, float* __restrict__ Wt) {
    __shared__ float tile[32][33];
    int bx = blockIdx.x * 32, by = blockIdx.y * 32;
    int tx = threadIdx.x, ty = threadIdx.y;   // 32 x 8
    #pragma unroll
    for (int i = 0; i < 32; i += 8)
        tile[ty + i][tx] = W[(size_t)(by + ty + i) * DIM + bx + tx];
    __syncthreads();
    #pragma unroll
    for (int i = 0; i < 32; i += 8)
        Wt[(size_t)(bx + ty + i) * DIM + by + tx] = __uint_as_float(f2tf32(tile[tx][ty + i]));
}

// ---------------- cp.async-pipelined TF32 mma.sync GEMM ----------------
// C[M,1024] = sum_chunks A_c[M,1024] @ Wt_c[n][k]^T + bias0 (+bias1)
#define LDR   20
#define ATILE (128 * LDR)
#define STAGE_FLOATS (2 * ATILE)
#define NSTAGE 3
#define GEMM_SMEM_DYN (NSTAGE * STAGE_FLOATS * 4)   // 61440 B

template <int CHUNKS>
__global__ __launch_bounds__(256, 2) void gemm_tf32_cpasync(
    const float* __restrict__ A0, const float* __restrict__ A1,
    const float* __restrict__ Wt0, const float* __restrict__ Wt1,
    const float* __restrict__ bias0, const float* __restrict__ bias1,
    float* __restrict__ C, int M)
{
    extern __shared__ float smem[];
    const uint32_t smem_u32 = smem_to_u32(smem);

    const int t      = threadIdx.x;
    const int lane   = t & 31;
    const int warp   = t >> 5;
    const int warp_m = warp >> 2;
    const int warp_n = warp & 3;
    const int g      = lane >> 2;
    const int tid4   = lane & 3;
    const int bm     = blockIdx.y * 128;
    const int bn     = blockIdx.x * 128;

    const int KT = 64 * CHUNKS;

    const int s_row0 = t >> 2;
    const int s_row1 = (t + 256) >> 2;
    const int s_c    = t & 3;

    auto stage = [&](int kt, int buf) {
        const float* Asrc = (CHUNKS == 2 && kt >= 64) ? A1 : A0;
        const float* Wsrc = (CHUNKS == 2 && kt >= 64) ? Wt1 : Wt0;
        const int k0 = (kt & 63) * 16;
        const uint32_t abase = smem_u32 + (uint32_t)buf * (STAGE_FLOATS * 4);
        const uint32_t bbase = abase + ATILE * 4;
        #pragma unroll
        for (int i = 0; i < 2; i++) {
            int row = i ? s_row1 : s_row0;
            int gm = bm + row;
            int gmc = (gm < M) ? gm : 0;
            cp_async16(abase + (uint32_t)(row * LDR + s_c * 4) * 4,
                       Asrc + (size_t)gmc * DIM + k0 + s_c * 4,
                       (gm < M) ? 16u : 0u);
            int gn = bn + row;
            cp_async16(bbase + (uint32_t)(row * LDR + s_c * 4) * 4,
                       Wsrc + (size_t)gn * DIM + k0 + s_c * 4, 16u);
        }
    };

    float c[4][4][4];
    #pragma unroll
    for (int mt = 0; mt < 4; mt++)
        #pragma unroll
        for (int nt = 0; nt < 4; nt++)
            #pragma unroll
            for (int r = 0; r < 4; r++) c[mt][nt][r] = 0.f;

    auto compute = [&](int buf) {
        const uint32_t* As = reinterpret_cast<const uint32_t*>(smem) + buf * STAGE_FLOATS;
        const uint32_t* Bs = As + ATILE;
        #pragma unroll
        for (int ks = 0; ks < 2; ks++) {
            const int kb = ks * 8;
            uint32_t a[4][4], b[4][2];
            #pragma unroll
            for (int mt = 0; mt < 4; mt++) {
                const uint32_t* ar0 = As + (warp_m * 64 + mt * 16 + g) * LDR + kb + tid4;
                const uint32_t* ar1 = ar0 + 8 * LDR;
                a[mt][0] = ar0[0]; a[mt][1] = ar1[0];
                a[mt][2] = ar0[4]; a[mt][3] = ar1[4];
            }
            #pragma unroll
            for (int nt = 0; nt < 4; nt++) {
                const uint32_t* br = Bs + (warp_n * 32 + nt * 8 + g) * LDR + kb + tid4;
                b[nt][0] = br[0]; b[nt][1] = br[4];
            }
            #pragma unroll
            for (int mt = 0; mt < 4; mt++)
                #pragma unroll
                for (int nt = 0; nt < 4; nt++)
                    mma_tf32(c[mt][nt][0], c[mt][nt][1], c[mt][nt][2], c[mt][nt][3],
                             a[mt][0], a[mt][1], a[mt][2], a[mt][3],
                             b[nt][0], b[nt][1]);
        }
    };

    stage(0, 0); cp_async_commit();
    stage(1, 1); cp_async_commit();

    int buf = 0;
    for (int kt = 0; kt < KT; ++kt) {
        cp_async_wait<1>();
        __syncthreads();
        compute(buf);
        if (kt + 2 < KT) stage(kt + 2, (buf + 2) % NSTAGE);
        cp_async_commit();
        buf = (buf + 1) % NSTAGE;
    }

    #pragma unroll
    for (int mt = 0; mt < 4; mt++) {
        int r0 = bm + warp_m * 64 + mt * 16 + g;
        int r1 = r0 + 8;
        #pragma unroll
        for (int nt = 0; nt < 4; nt++) {
            int col = bn + warp_n * 32 + nt * 8 + tid4 * 2;
            float bv0 = bias0[col], bv1 = bias0[col + 1];
            if (CHUNKS == 2) { bv0 += bias1[col]; bv1 += bias1[col + 1]; }
            if (r0 < M) {
                float* p = &C[(size_t)r0 * DIM + col];
                p[0] = c[mt][nt][0] + bv0; p[1] = c[mt][nt][1] + bv1;
            }
            if (r1 < M) {
                float* p = &C[(size_t)r1 * DIM + col];
                p[0] = c[mt][nt][2] + bv0; p[1] = c[mt][nt][3] + bv1;
            }
        }
    }
}

// ---------------- launch (single capture stream) ----------------
static void run_sort(int rel, const int* src, const int* dst)
{
    zero_deg_kernel<<<(N_NODE + 255) / 256, 256>>>(rel);
    hist_kernel<<<(N_EDGE + 255) / 256, 256>>>(rel, dst);
    scan_block_kernel<<<NBLK_SCAN, 1024>>>(rel);
    scan_add_kernel<<<NBLK_SCAN, 1024>>>(rel);
    scatter_kernel<<<(N_EDGE + 255) / 256, 256>>>(rel, src, dst);
}

extern "C" void kernel_launch(void* const* d_in, const int* in_sizes, int n_in,
                              void* d_out, int out_size)
{
    const float* x_drug = (const float*)d_in[0];
    const float* x_prot = (const float*)d_in[1];
    const float* W_ddi  = (const float*)d_in[2];
    const float* b_ddi  = (const float*)d_in[3];
    const float* W_dpi  = (const float*)d_in[4];
    const float* b_dpi  = (const float*)d_in[5];
    const float* W_ppi  = (const float*)d_in[6];
    const float* b_ppi  = (const float*)d_in[7];
    const int* src_ddi  = (const int*)d_in[8];
    const int* dst_ddi  = (const int*)d_in[9];
    const int* src_dpi  = (const int*)d_in[10];
    const int* dst_dpi  = (const int*)d_in[11];
    const int* src_ppi  = (const int*)d_in[12];
    const int* dst_ppi  = (const int*)d_in[13];

    float* out_drug = (float*)d_out;
    float* out_prot = out_drug + (size_t)N_NODE * DIM;

    float* agg0; cudaGetSymbolAddress((void**)&agg0, g_agg0);   // dpi
    float* agg1; cudaGetSymbolAddress((void**)&agg1, g_agg1);   // ppi
    float* agg2; cudaGetSymbolAddress((void**)&agg2, g_agg2);   // ddi
    float* wt0;  cudaGetSymbolAddress((void**)&wt0,  g_wt0);
    float* wt1;  cudaGetSymbolAddress((void**)&wt1,  g_wt1);
    float* wt2;  cudaGetSymbolAddress((void**)&wt2,  g_wt2);

    cudaFuncSetAttribute(gemm_tf32_cpasync<1>,
                         cudaFuncAttributeMaxDynamicSharedMemorySize, GEMM_SMEM_DYN);
    cudaFuncSetAttribute(gemm_tf32_cpasync<2>,
                         cudaFuncAttributeMaxDynamicSharedMemorySize, GEMM_SMEM_DYN);

    dim3 tgrid(32, 32), tblk(32, 8);
    dim3 grid(DIM / 128, (N_NODE + 127) / 128);

    // ---- dpi sort (launches #0-#4), then dpi agg chunk0 at launch #5 (ncu -s 5 target) ----
    run_sort(0, src_dpi, dst_dpi);
    aggregate_chunk_kernel<<<N_NODE, 64>>>(0, 0, x_drug, agg0);

    // ---- ddi sort, then interleave dpi/ddi chunks so each x_drug slice is shared in L2 ----
    run_sort(2, src_ddi, dst_ddi);
    aggregate_chunk_kernel<<<N_NODE, 64>>>(2, 0, x_drug, agg2);
    for (int c = 1; c < DCHUNKS; ++c) {
        aggregate_chunk_kernel<<<N_NODE, 64>>>(0, c, x_drug, agg0);
        aggregate_chunk_kernel<<<N_NODE, 64>>>(2, c, x_drug, agg2);
    }

    // ---- ppi sort + aggregate ----
    run_sort(1, src_ppi, dst_ppi);
    for (int c = 0; c < DCHUNKS; ++c)
        aggregate_chunk_kernel<<<N_NODE, 64>>>(1, c, x_prot, agg1);

    // ---- weight transposes ----
    transpose_round_kernel<<<tgrid, tblk>>>(W_dpi, wt0);
    transpose_round_kernel<<<tgrid, tblk>>>(W_ppi, wt1);
    transpose_round_kernel<<<tgrid, tblk>>>(W_ddi, wt2);

    // ---- GEMMs: prot = fused K=2048 (dpi + ppi); drug = ddi ----
    gemm_tf32_cpasync<2><<<grid, 256, GEMM_SMEM_DYN>>>(
        agg0, agg1, wt0, wt1, b_dpi, b_ppi, out_prot, N_NODE);
    gemm_tf32_cpasync<1><<<grid, 256, GEMM_SMEM_DYN>>>(
        agg2, nullptr, wt2, nullptr, b_ddi, nullptr, out_drug, N_NODE);
}